// round 8
// baseline (speedup 1.0000x reference)
#include <cuda_runtime.h>

// ---------------------------------------------------------------------------
// ClientBackbone: 4x (conv1x1 [+ bilinear 2x upsample] [+ block shuffle])
// plus passthrough copies.
//
// Conv and bilinear-upsample commute (both linear), so convs run at source
// resolution (4x fewer FLOPs for layers 1-3) and the upsample runs after.
//
// GEMM with packed f32x2 FMA (FFMA2, 2x fp32 MAC rate on sm_103a),
// 128-thread blocks, 4m x 8n(packed) microtile, double-buffered smem with
// global->reg prefetch. Upsample processes an even/odd output-pixel pair per
// thread with a single float2 store (pair shares source columns and, for
// aux1, the same shuffle block since 28 is even).
// ---------------------------------------------------------------------------

static constexpr int BATCH = 64;

// Scratch for conv outputs at source resolution (allocation-free rule).
__device__ float g1_scratch[BATCH * 64 * 28 * 28];    // 3,211,264
__device__ float g2_scratch[BATCH * 128 * 14 * 14];   // 1,605,632
__device__ float g3_scratch[BATCH * 256 * 7 * 7];     //   802,816

#define FMA_F32X2(d, a, b) \
    asm("fma.rn.f32x2 %0, %1, %2, %0;" : "+l"(d) : "l"(a), "l"(b))

#define UNPACK_F32X2(lo, hi, in) \
    asm("mov.b64 {%0, %1}, %2;" : "=f"(lo), "=f"(hi) : "l"(in))

#define PACK_DUP_F32X2(out, v) \
    asm("mov.b64 %0, {%1, %1};" : "=l"(out) : "f"(v))

// ---------------------------------------------------------------------------
// conv1x1: out[b, m, p] = sum_k w[m, k] * f[b, k, p] + bias[m]
// GEMM over flat n = b*P + p (N = 64*P, divisible by 64).
// Block: 128 threads, tile 64(M) x 64(N), K-tile 16.
// Thread microtile: 4(m) x 8(n), n packed into 4 f32x2 accumulators per m.
// ---------------------------------------------------------------------------
template <int M, int K, int P>
__global__ __launch_bounds__(128) void conv1x1_kernel(
    const float* __restrict__ f, const float* __restrict__ w,
    const float* __restrict__ bias, float* __restrict__ out)
{
    __shared__ alignas(16) unsigned long long ws2[2][16][64]; // {w,w} pairs, 16KB
    __shared__ alignas(16) float fs[2][16][64];               // 8KB
    __shared__ int foff[64];
    __shared__ int ooff[64];

    const int tid = threadIdx.x;
    const int n0 = blockIdx.x * 64;
    const int m0 = blockIdx.y * 64;

    if (tid < 64) {
        int nn = n0 + tid;
        int b = nn / P;
        int p = nn - b * P;
        foff[tid] = b * (K * P) + p;
        ooff[tid] = b * (M * P) + p;
    }

    const int tn = tid & 7;        // 0..7  -> n group of 8
    const int tm = tid >> 3;       // 0..15 -> m group of 4

    // W load mapping: thread t handles row m = t>>1, k-half (t&1)*8.
    const int wlm = tid >> 1;
    const int wlk = (tid & 1) * 8;
    // F load mapping: e = tid + 128*i -> k = e>>6, n = e&63.

    unsigned long long acc[4][4];
#pragma unroll
    for (int i = 0; i < 4; i++)
#pragma unroll
        for (int j = 0; j < 4; j++) acc[i][j] = 0ULL;

    float wreg[8];
    float freg[8];

    __syncthreads();   // foff/ooff ready (needed by F prefetch below)

    // Prefetch tile 0
    {
        const float* wp = w + (m0 + wlm) * K + wlk;
#pragma unroll
        for (int i = 0; i < 8; i++) wreg[i] = wp[i];
#pragma unroll
        for (int i = 0; i < 8; i++) {
            int e = tid + 128 * i;
            freg[i] = f[foff[e & 63] + (e >> 6) * P];
        }
    }
    // Store tile 0
#pragma unroll
    for (int i = 0; i < 8; i++)
        PACK_DUP_F32X2(ws2[0][wlk + i][wlm], wreg[i]);
#pragma unroll
    for (int i = 0; i < 8; i++) {
        int e = tid + 128 * i;
        fs[0][e >> 6][e & 63] = freg[i];
    }
    __syncthreads();

    constexpr int NT = K / 16;
#pragma unroll 1
    for (int kt = 0; kt < NT; kt++) {
        const int cur = kt & 1;

        if (kt + 1 < NT) {
            const int k0 = (kt + 1) * 16;
            const float* wp = w + (m0 + wlm) * K + k0 + wlk;
#pragma unroll
            for (int i = 0; i < 8; i++) wreg[i] = wp[i];
#pragma unroll
            for (int i = 0; i < 8; i++) {
                int e = tid + 128 * i;
                freg[i] = f[foff[e & 63] + (k0 + (e >> 6)) * P];
            }
        }

#pragma unroll
        for (int k = 0; k < 16; k++) {
            const ulonglong2 wA =
                *reinterpret_cast<const ulonglong2*>(&ws2[cur][k][tm * 4]);
            const ulonglong2 wB =
                *reinterpret_cast<const ulonglong2*>(&ws2[cur][k][tm * 4 + 2]);
            const ulonglong2 fA =
                *reinterpret_cast<const ulonglong2*>(&fs[cur][k][tn * 8]);
            const ulonglong2 fB =
                *reinterpret_cast<const ulonglong2*>(&fs[cur][k][tn * 8 + 4]);

            FMA_F32X2(acc[0][0], wA.x, fA.x);
            FMA_F32X2(acc[0][1], wA.x, fA.y);
            FMA_F32X2(acc[0][2], wA.x, fB.x);
            FMA_F32X2(acc[0][3], wA.x, fB.y);
            FMA_F32X2(acc[1][0], wA.y, fA.x);
            FMA_F32X2(acc[1][1], wA.y, fA.y);
            FMA_F32X2(acc[1][2], wA.y, fB.x);
            FMA_F32X2(acc[1][3], wA.y, fB.y);
            FMA_F32X2(acc[2][0], wB.x, fA.x);
            FMA_F32X2(acc[2][1], wB.x, fA.y);
            FMA_F32X2(acc[2][2], wB.x, fB.x);
            FMA_F32X2(acc[2][3], wB.x, fB.y);
            FMA_F32X2(acc[3][0], wB.y, fA.x);
            FMA_F32X2(acc[3][1], wB.y, fA.y);
            FMA_F32X2(acc[3][2], wB.y, fB.x);
            FMA_F32X2(acc[3][3], wB.y, fB.y);
        }

        if (kt + 1 < NT) {
            const int nxt = 1 - cur;
#pragma unroll
            for (int i = 0; i < 8; i++)
                PACK_DUP_F32X2(ws2[nxt][wlk + i][wlm], wreg[i]);
#pragma unroll
            for (int i = 0; i < 8; i++) {
                int e = tid + 128 * i;
                fs[nxt][e >> 6][e & 63] = freg[i];
            }
            __syncthreads();
        }
    }

    // Epilogue
#pragma unroll
    for (int im = 0; im < 4; im++) {
        const int m = m0 + tm * 4 + im;
        const float bv = bias[m];
        float* op = out + m * P;
#pragma unroll
        for (int jp = 0; jp < 4; jp++) {
            float lo, hi;
            UNPACK_F32X2(lo, hi, acc[im][jp]);
            op[ooff[tn * 8 + 2 * jp]]     = lo + bv;
            op[ooff[tn * 8 + 2 * jp + 1]] = hi + bv;
        }
    }
}

// ---------------------------------------------------------------------------
// Bilinear 2x upsample, half-pixel (align_corners=False), clamped edges.
// One thread per even/odd x-pair: x0=2j (frac 0.75 from col j-1..j) and
// x1=2j+1 (frac 0.25 from col j..j+1); shared columns, one float2 store.
// For SHUF (aux1): both pixels of the pair are in the same 28-block
// (x>=28 <=> j>=14), so cs = perms[blk*64 + c] is computed once.
// ---------------------------------------------------------------------------
template <int C, int SI, bool SHUF>
__global__ __launch_bounds__(256) void upsample2x_kernel(
    const float* __restrict__ g, float* __restrict__ out,
    const int* __restrict__ perms)
{
    constexpr int S = SI * 2;
    constexpr int TOTAL = BATCH * C * S * SI;   // pairs
    int t = blockIdx.x * 256 + threadIdx.x;
    if (t >= TOTAL) return;

    int j = t % SI;
    int y = (t / SI) % S;
    int c = (t / (SI * S)) % C;
    int b = t / (SI * S * C);

    int cs = c;
    if (SHUF) {
        int blk = ((y >= 28) ? 2 : 0) + ((j >= 14) ? 1 : 0);
        cs = perms[blk * 64 + c];
    }
    const float* gp = g + (b * C + cs) * (SI * SI);

    int iy = (y - 1) >> 1;
    int iy0 = iy < 0 ? 0 : iy;
    int iy1 = (iy + 1 > SI - 1) ? SI - 1 : iy + 1;
    float fy = (y & 1) ? 0.25f : 0.75f;

    int jm = j > 0 ? j - 1 : 0;
    int jp = j < SI - 1 ? j + 1 : SI - 1;

    const float* r0 = gp + iy0 * SI;
    const float* r1 = gp + iy1 * SI;
    float a0 = r0[jm], a1 = r0[j], a2 = r0[jp];
    float b0 = r1[jm], b1 = r1[j], b2 = r1[jp];

    // even pixel (x=2j): v00 = col jm, v01 = col j, fx = 0.75
    float topE = a0 + 0.75f * (a1 - a0);
    float botE = b0 + 0.75f * (b1 - b0);
    // odd pixel (x=2j+1): v00 = col j, v01 = col jp, fx = 0.25
    float topO = a1 + 0.25f * (a2 - a1);
    float botO = b1 + 0.25f * (b2 - b1);

    float2 res;
    res.x = topE + fy * (botE - topE);
    res.y = topO + fy * (botO - topO);

    long o = (((long)(b * C + c) * S + y) * S) + 2 * j;
    *reinterpret_cast<float2*>(out + o) = res;
}

// ---------------------------------------------------------------------------
// kernel_launch
// ---------------------------------------------------------------------------
extern "C" void kernel_launch(void* const* d_in, const int* in_sizes, int n_in,
                              void* d_out, int out_size)
{
    (void)in_sizes; (void)n_in; (void)out_size;

    const float* f1      = (const float*)d_in[0];
    const float* f2      = (const float*)d_in[1];
    const float* f3      = (const float*)d_in[2];
    const float* f4      = (const float*)d_in[3];
    const float* x_final = (const float*)d_in[4];
    const float* cw1     = (const float*)d_in[5];
    const float* cb1     = (const float*)d_in[6];
    const float* cw2     = (const float*)d_in[7];
    const float* cb2     = (const float*)d_in[8];
    const float* cw3     = (const float*)d_in[9];
    const float* cb3     = (const float*)d_in[10];
    const float* cw4     = (const float*)d_in[11];
    const float* cb4     = (const float*)d_in[12];
    const float* w1      = (const float*)d_in[13];
    const float* w2      = (const float*)d_in[14];
    const float* w3      = (const float*)d_in[15];
    const float* w4      = (const float*)d_in[16];
    const int*   perms   = (const int*)  d_in[17];

    float* out = (float*)d_out;

    float *g1, *g2, *g3;
    cudaGetSymbolAddress((void**)&g1, g1_scratch);
    cudaGetSymbolAddress((void**)&g2, g2_scratch);
    cudaGetSymbolAddress((void**)&g3, g3_scratch);

    // Output offsets (floats)
    constexpr long OFF_XF   = 0;
    constexpr long OFF_AUX1 = 32768;
    constexpr long OFF_AUX2 = 12877824;
    constexpr long OFF_AUX3 = 19300352;
    constexpr long OFF_AUX4 = 22511616;
    constexpr long OFF_W1   = 24117248;
    constexpr long OFF_W2   = 24317952;
    constexpr long OFF_W3   = 24418304;
    constexpr long OFF_W4   = 24468480;

    // Passthrough copies
    cudaMemcpyAsync(out + OFF_XF, x_final, 32768 * sizeof(float),
                    cudaMemcpyDeviceToDevice, 0);
    cudaMemcpyAsync(out + OFF_W1, w1, 200704 * sizeof(float),
                    cudaMemcpyDeviceToDevice, 0);
    cudaMemcpyAsync(out + OFF_W2, w2, 100352 * sizeof(float),
                    cudaMemcpyDeviceToDevice, 0);
    cudaMemcpyAsync(out + OFF_W3, w3, 50176 * sizeof(float),
                    cudaMemcpyDeviceToDevice, 0);
    cudaMemcpyAsync(out + OFF_W4, w4, 25088 * sizeof(float),
                    cudaMemcpyDeviceToDevice, 0);

    // Convs at source resolution. Flat N = 64*P, tiles of 64.
    conv1x1_kernel<64, 64, 784><<<dim3(784, 1), 128>>>(f1, cw1, cb1, g1);
    conv1x1_kernel<128, 128, 196><<<dim3(196, 2), 128>>>(f2, cw2, cb2, g2);
    conv1x1_kernel<256, 128, 49><<<dim3(49, 4), 128>>>(f3, cw3, cb3, g3);
    // aux4: no upsample (7 -> 7), write output region directly.
    conv1x1_kernel<512, 512, 49><<<dim3(49, 8), 128>>>(f4, cw4, cb4,
                                                       out + OFF_AUX4);

    // Upsamples (pair-per-thread; aux1 fused with channel shuffle).
    // Pairs: aux1 64*64*56*28 = 6,422,528 -> 25088 blocks
    //        aux2 64*128*28*14 = 3,211,264 -> 12544 blocks
    //        aux3 64*256*14*7  = 1,605,632 ->  6272 blocks
    upsample2x_kernel<64, 28, true><<<25088, 256>>>(g1, out + OFF_AUX1, perms);
    upsample2x_kernel<128, 14, false><<<12544, 256>>>(g2, out + OFF_AUX2, nullptr);
    upsample2x_kernel<256, 7, false><<<6272, 256>>>(g3, out + OFF_AUX3, nullptr);
}

// round 11
// speedup vs baseline: 1.1876x; 1.1876x over previous
#include <cuda_runtime.h>

// ---------------------------------------------------------------------------
// ClientBackbone: 4x (conv1x1 [+ bilinear 2x upsample] [+ block shuffle])
// plus passthrough copies.
//
// Conv and bilinear-upsample commute (both linear), so convs run at source
// resolution (4x fewer FLOPs for layers 1-3) and the upsample runs after.
//
// Scalar-FFMA GEMM (R1 structure; FFMA2 measured zero-gain on the fma pipe
// in R8), 256 threads/block, M-tile = 16*MT. MT=2 for L2-L4 doubles the
// block count (R1/R8 evidence: these layers are occupancy/issue-limited,
// not pipe-limited). Upsample: even/odd pixel-pair per thread, one float2
// store.
// ---------------------------------------------------------------------------

static constexpr int BATCH = 64;

// Scratch for conv outputs at source resolution (allocation-free rule).
__device__ float g1_scratch[BATCH * 64 * 28 * 28];    // 3,211,264
__device__ float g2_scratch[BATCH * 128 * 14 * 14];   // 1,605,632
__device__ float g3_scratch[BATCH * 256 * 7 * 7];     //   802,816

// ---------------------------------------------------------------------------
// conv1x1: out[b, m, p] = sum_k w[m, k] * f[b, k, p] + bias[m]
// GEMM over flat n = b*P + p (N = 64*P, divisible by 64).
// 256 threads, tile (16*MT)M x 64N, K-tile 16, microtile MT(m) x 4(n).
// ---------------------------------------------------------------------------
template <int M, int K, int P, int MT>
__global__ __launch_bounds__(256) void conv1x1_kernel(
    const float* __restrict__ f, const float* __restrict__ w,
    const float* __restrict__ bias, float* __restrict__ out)
{
    constexpr int TM = 16 * MT;
    __shared__ float ws[16][TM + 4];   // padded row, 16B-aligned rows
    __shared__ float fs[16][64];
    __shared__ int   foff[64];         // per-n input base offset (b*K*P + p)
    __shared__ int   ooff[64];         // per-n output base offset (b*M*P + p)

    const int tid = threadIdx.x;
    const int n0 = blockIdx.x * 64;
    const int m0 = blockIdx.y * TM;

    if (tid < 64) {
        int nn = n0 + tid;
        int b = nn / P;
        int p = nn - b * P;
        foff[tid] = b * (K * P) + p;
        ooff[tid] = b * (M * P) + p;
    }
    __syncthreads();

    const int tm = tid >> 4;   // 0..15 (m groups of MT)
    const int tp = tid & 15;   // 0..15 (n groups of 4)

    float acc[MT][4];
#pragma unroll
    for (int i = 0; i < MT; i++)
#pragma unroll
        for (int j = 0; j < 4; j++) acc[i][j] = 0.0f;

    for (int k0 = 0; k0 < K; k0 += 16) {
        // Load W tile: 16*TM elements, MT per thread, consecutive threads
        // walk k (coalesced 64B segments).
#pragma unroll
        for (int i = 0; i < MT; i++) {
            int e = tid + 256 * i;
            ws[e & 15][e >> 4] = w[(m0 + (e >> 4)) * K + (k0 + (e & 15))];
        }
        // Load F tile: 1024 elements, 4 per thread, consecutive threads
        // walk n (coalesced within batch).
#pragma unroll
        for (int i = 0; i < 4; i++) {
            int e = tid + 256 * i;
            fs[e >> 6][e & 63] = f[foff[e & 63] + (k0 + (e >> 6)) * P];
        }
        __syncthreads();

#pragma unroll
        for (int k = 0; k < 16; k++) {
            float4 fv = *reinterpret_cast<const float4*>(&fs[k][tp * 4]);
            float wv[MT];
            if constexpr (MT == 4) {
                float4 t = *reinterpret_cast<const float4*>(&ws[k][tm * 4]);
                wv[0] = t.x; wv[1] = t.y; wv[2] = t.z; wv[3] = t.w;
            } else {
                float2 t = *reinterpret_cast<const float2*>(&ws[k][tm * 2]);
                wv[0] = t.x; wv[1] = t.y;
            }
#pragma unroll
            for (int im = 0; im < MT; im++) {
                acc[im][0] += wv[im] * fv.x;
                acc[im][1] += wv[im] * fv.y;
                acc[im][2] += wv[im] * fv.z;
                acc[im][3] += wv[im] * fv.w;
            }
        }
        __syncthreads();
    }

#pragma unroll
    for (int im = 0; im < MT; im++) {
        int m = m0 + tm * MT + im;
        float bv = bias[m];
        float* op = out + m * P;
#pragma unroll
        for (int ip = 0; ip < 4; ip++) {
            op[ooff[tp * 4 + ip]] = acc[im][ip] + bv;
        }
    }
}

// ---------------------------------------------------------------------------
// Bilinear 2x upsample, half-pixel (align_corners=False), clamped edges.
// One thread per even/odd x-pair: x0=2j (frac 0.75 from col j-1..j) and
// x1=2j+1 (frac 0.25 from col j..j+1); shared columns, one float2 store.
// For SHUF (aux1): both pixels of the pair are in the same 28-block
// (x>=28 <=> j>=14), so cs = perms[blk*64 + c] is computed once.
// ---------------------------------------------------------------------------
template <int C, int SI, bool SHUF>
__global__ __launch_bounds__(256) void upsample2x_kernel(
    const float* __restrict__ g, float* __restrict__ out,
    const int* __restrict__ perms)
{
    constexpr int S = SI * 2;
    constexpr int TOTAL = BATCH * C * S * SI;   // pairs
    int t = blockIdx.x * 256 + threadIdx.x;
    if (t >= TOTAL) return;

    int j = t % SI;
    int y = (t / SI) % S;
    int c = (t / (SI * S)) % C;
    int b = t / (SI * S * C);

    int cs = c;
    if (SHUF) {
        int blk = ((y >= 28) ? 2 : 0) + ((j >= 14) ? 1 : 0);
        cs = perms[blk * 64 + c];
    }
    const float* gp = g + (b * C + cs) * (SI * SI);

    int iy = (y - 1) >> 1;
    int iy0 = iy < 0 ? 0 : iy;
    int iy1 = (iy + 1 > SI - 1) ? SI - 1 : iy + 1;
    float fy = (y & 1) ? 0.25f : 0.75f;

    int jm = j > 0 ? j - 1 : 0;
    int jp = j < SI - 1 ? j + 1 : SI - 1;

    const float* r0 = gp + iy0 * SI;
    const float* r1 = gp + iy1 * SI;
    float a0 = r0[jm], a1 = r0[j], a2 = r0[jp];
    float b0 = r1[jm], b1 = r1[j], b2 = r1[jp];

    // even pixel (x=2j): v00 = col jm, v01 = col j, fx = 0.75
    float topE = a0 + 0.75f * (a1 - a0);
    float botE = b0 + 0.75f * (b1 - b0);
    // odd pixel (x=2j+1): v00 = col j, v01 = col jp, fx = 0.25
    float topO = a1 + 0.25f * (a2 - a1);
    float botO = b1 + 0.25f * (b2 - b1);

    float2 res;
    res.x = topE + fy * (botE - topE);
    res.y = topO + fy * (botO - topO);

    long o = (((long)(b * C + c) * S + y) * S) + 2 * j;
    *reinterpret_cast<float2*>(out + o) = res;
}

// ---------------------------------------------------------------------------
// kernel_launch
// ---------------------------------------------------------------------------
extern "C" void kernel_launch(void* const* d_in, const int* in_sizes, int n_in,
                              void* d_out, int out_size)
{
    (void)in_sizes; (void)n_in; (void)out_size;

    const float* f1      = (const float*)d_in[0];
    const float* f2      = (const float*)d_in[1];
    const float* f3      = (const float*)d_in[2];
    const float* f4      = (const float*)d_in[3];
    const float* x_final = (const float*)d_in[4];
    const float* cw1     = (const float*)d_in[5];
    const float* cb1     = (const float*)d_in[6];
    const float* cw2     = (const float*)d_in[7];
    const float* cb2     = (const float*)d_in[8];
    const float* cw3     = (const float*)d_in[9];
    const float* cb3     = (const float*)d_in[10];
    const float* cw4     = (const float*)d_in[11];
    const float* cb4     = (const float*)d_in[12];
    const float* w1      = (const float*)d_in[13];
    const float* w2      = (const float*)d_in[14];
    const float* w3      = (const float*)d_in[15];
    const float* w4      = (const float*)d_in[16];
    const int*   perms   = (const int*)  d_in[17];

    float* out = (float*)d_out;

    float *g1, *g2, *g3;
    cudaGetSymbolAddress((void**)&g1, g1_scratch);
    cudaGetSymbolAddress((void**)&g2, g2_scratch);
    cudaGetSymbolAddress((void**)&g3, g3_scratch);

    // Output offsets (floats)
    constexpr long OFF_XF   = 0;
    constexpr long OFF_AUX1 = 32768;
    constexpr long OFF_AUX2 = 12877824;
    constexpr long OFF_AUX3 = 19300352;
    constexpr long OFF_AUX4 = 22511616;
    constexpr long OFF_W1   = 24117248;
    constexpr long OFF_W2   = 24317952;
    constexpr long OFF_W3   = 24418304;
    constexpr long OFF_W4   = 24468480;

    // Passthrough copies
    cudaMemcpyAsync(out + OFF_XF, x_final, 32768 * sizeof(float),
                    cudaMemcpyDeviceToDevice, 0);
    cudaMemcpyAsync(out + OFF_W1, w1, 200704 * sizeof(float),
                    cudaMemcpyDeviceToDevice, 0);
    cudaMemcpyAsync(out + OFF_W2, w2, 100352 * sizeof(float),
                    cudaMemcpyDeviceToDevice, 0);
    cudaMemcpyAsync(out + OFF_W3, w3, 50176 * sizeof(float),
                    cudaMemcpyDeviceToDevice, 0);
    cudaMemcpyAsync(out + OFF_W4, w4, 25088 * sizeof(float),
                    cudaMemcpyDeviceToDevice, 0);

    // Convs at source resolution. Flat N = 64*P (x-tiles of 64).
    // MT=4 -> 64-row M-tiles (L1: grid already large).
    // MT=2 -> 32-row M-tiles (L2-L4: doubles block count for occupancy).
    conv1x1_kernel<64, 64, 784, 4><<<dim3(784, 1), 256>>>(f1, cw1, cb1, g1);
    conv1x1_kernel<128, 128, 196, 2><<<dim3(196, 4), 256>>>(f2, cw2, cb2, g2);
    conv1x1_kernel<256, 128, 49, 2><<<dim3(49, 8), 256>>>(f3, cw3, cb3, g3);
    // aux4: no upsample (7 -> 7), write output region directly.
    conv1x1_kernel<512, 512, 49, 2><<<dim3(49, 16), 256>>>(f4, cw4, cb4,
                                                           out + OFF_AUX4);

    // Upsamples (pair-per-thread; aux1 fused with channel shuffle).
    // Pairs: aux1 6,422,528 -> 25088 blocks; aux2 3,211,264 -> 12544;
    //        aux3 1,605,632 -> 6272.
    upsample2x_kernel<64, 28, true><<<25088, 256>>>(g1, out + OFF_AUX1, perms);
    upsample2x_kernel<128, 14, false><<<12544, 256>>>(g2, out + OFF_AUX2, nullptr);
    upsample2x_kernel<256, 7, false><<<6272, 256>>>(g3, out + OFF_AUX3, nullptr);
}

// round 12
// speedup vs baseline: 1.4874x; 1.2524x over previous
#include <cuda_runtime.h>

// ---------------------------------------------------------------------------
// ClientBackbone: 4x (conv1x1 [+ bilinear 2x upsample] [+ block shuffle])
// plus passthrough copies.
//
// Conv and bilinear-upsample commute (both linear), so convs run at source
// resolution (4x fewer FLOPs for layers 1-3) and the upsample runs after.
//
// R12: R1's proven tiling (64x64 tile, 256 threads, 4x4 microtile, scalar
// FFMA) + double-buffered smem with register prefetch and ONE barrier per
// k-tile. Evidence: fma-pipe cycles are conserved across R1/R8/R11 (~22us
// for L4), so runtime = fma_cycles / fma%%; the lever is removing exposed
// LDG latency + barrier overhead, not occupancy or packed FMA.
// Upsample: even/odd pixel-pair per thread, one float2 store (validated R8).
// ---------------------------------------------------------------------------

static constexpr int BATCH = 64;

// Scratch for conv outputs at source resolution (allocation-free rule).
__device__ float g1_scratch[BATCH * 64 * 28 * 28];    // 3,211,264
__device__ float g2_scratch[BATCH * 128 * 14 * 14];   // 1,605,632
__device__ float g3_scratch[BATCH * 256 * 7 * 7];     //   802,816

// ---------------------------------------------------------------------------
// conv1x1: out[b, m, p] = sum_k w[m, k] * f[b, k, p] + bias[m]
// GEMM over flat n = b*P + p (N = 64*P, divisible by 64).
// 256 threads, tile 64M x 64N, K-tile 16, microtile 4(m) x 4(n).
// Double-buffered: LDG of tile kt+1 issues before the compute of tile kt;
// single __syncthreads per k-tile.
// ---------------------------------------------------------------------------
template <int M, int K, int P>
__global__ __launch_bounds__(256) void conv1x1_kernel(
    const float* __restrict__ f, const float* __restrict__ w,
    const float* __restrict__ bias, float* __restrict__ out)
{
    __shared__ float ws[2][16][68];   // [buf][k][m], padded rows
    __shared__ float fs[2][16][64];   // [buf][k][n]
    __shared__ int   foff[64];        // per-n input base offset (b*K*P + p)
    __shared__ int   ooff[64];        // per-n output base offset (b*M*P + p)

    const int tid = threadIdx.x;
    const int n0 = blockIdx.x * 64;
    const int m0 = blockIdx.y * 64;

    if (tid < 64) {
        int nn = n0 + tid;
        int b = nn / P;
        int p = nn - b * P;
        foff[tid] = b * (K * P) + p;
        ooff[tid] = b * (M * P) + p;
    }
    __syncthreads();   // foff/ooff ready for prefetch below

    const int tm = tid >> 4;   // 0..15 (m groups of 4)
    const int tp = tid & 15;   // 0..15 (n groups of 4)

    float acc[4][4];
#pragma unroll
    for (int i = 0; i < 4; i++)
#pragma unroll
        for (int j = 0; j < 4; j++) acc[i][j] = 0.0f;

    float wreg[4];
    float freg[4];

    // Prefetch tile 0 into registers
#pragma unroll
    for (int i = 0; i < 4; i++) {
        int e = tid + 256 * i;
        wreg[i] = w[(m0 + (e >> 4)) * K + (e & 15)];
        freg[i] = f[foff[e & 63] + (e >> 6) * P];
    }
    // Store tile 0 to buffer 0
#pragma unroll
    for (int i = 0; i < 4; i++) {
        int e = tid + 256 * i;
        ws[0][e & 15][e >> 4] = wreg[i];
        fs[0][e >> 6][e & 63] = freg[i];
    }
    __syncthreads();

    constexpr int NT = K / 16;
#pragma unroll 1
    for (int kt = 0; kt < NT; kt++) {
        const int cur = kt & 1;

        // Issue LDGs for tile kt+1 (latency overlapped with compute below)
        if (kt + 1 < NT) {
            const int k0 = (kt + 1) * 16;
#pragma unroll
            for (int i = 0; i < 4; i++) {
                int e = tid + 256 * i;
                wreg[i] = w[(m0 + (e >> 4)) * K + (k0 + (e & 15))];
                freg[i] = f[foff[e & 63] + (k0 + (e >> 6)) * P];
            }
        }

        // Compute 16 k-steps from the current buffer
#pragma unroll
        for (int k = 0; k < 16; k++) {
            float4 wv = *reinterpret_cast<const float4*>(&ws[cur][k][tm * 4]);
            float4 fv = *reinterpret_cast<const float4*>(&fs[cur][k][tp * 4]);
            acc[0][0] += wv.x * fv.x; acc[0][1] += wv.x * fv.y;
            acc[0][2] += wv.x * fv.z; acc[0][3] += wv.x * fv.w;
            acc[1][0] += wv.y * fv.x; acc[1][1] += wv.y * fv.y;
            acc[1][2] += wv.y * fv.z; acc[1][3] += wv.y * fv.w;
            acc[2][0] += wv.z * fv.x; acc[2][1] += wv.z * fv.y;
            acc[2][2] += wv.z * fv.z; acc[2][3] += wv.z * fv.w;
            acc[3][0] += wv.w * fv.x; acc[3][1] += wv.w * fv.y;
            acc[3][2] += wv.w * fv.z; acc[3][3] += wv.w * fv.w;
        }

        // Store tile kt+1 into the other buffer; one barrier per k-tile.
        if (kt + 1 < NT) {
            const int nxt = 1 - cur;
#pragma unroll
            for (int i = 0; i < 4; i++) {
                int e = tid + 256 * i;
                ws[nxt][e & 15][e >> 4] = wreg[i];
                fs[nxt][e >> 6][e & 63] = freg[i];
            }
            __syncthreads();
        }
    }

    // Epilogue
#pragma unroll
    for (int im = 0; im < 4; im++) {
        int m = m0 + tm * 4 + im;
        float bv = bias[m];
        float* op = out + m * P;
#pragma unroll
        for (int ip = 0; ip < 4; ip++) {
            op[ooff[tp * 4 + ip]] = acc[im][ip] + bv;
        }
    }
}

// ---------------------------------------------------------------------------
// Bilinear 2x upsample, half-pixel (align_corners=False), clamped edges.
// One thread per even/odd x-pair: x0=2j (frac 0.75 from col j-1..j) and
// x1=2j+1 (frac 0.25 from col j..j+1); shared columns, one float2 store.
// For SHUF (aux1): both pixels of the pair are in the same 28-block
// (x>=28 <=> j>=14), so cs = perms[blk*64 + c] is computed once.
// ---------------------------------------------------------------------------
template <int C, int SI, bool SHUF>
__global__ __launch_bounds__(256) void upsample2x_kernel(
    const float* __restrict__ g, float* __restrict__ out,
    const int* __restrict__ perms)
{
    constexpr int S = SI * 2;
    constexpr int TOTAL = BATCH * C * S * SI;   // pairs
    int t = blockIdx.x * 256 + threadIdx.x;
    if (t >= TOTAL) return;

    int j = t % SI;
    int y = (t / SI) % S;
    int c = (t / (SI * S)) % C;
    int b = t / (SI * S * C);

    int cs = c;
    if (SHUF) {
        int blk = ((y >= 28) ? 2 : 0) + ((j >= 14) ? 1 : 0);
        cs = perms[blk * 64 + c];
    }
    const float* gp = g + (b * C + cs) * (SI * SI);

    int iy = (y - 1) >> 1;
    int iy0 = iy < 0 ? 0 : iy;
    int iy1 = (iy + 1 > SI - 1) ? SI - 1 : iy + 1;
    float fy = (y & 1) ? 0.25f : 0.75f;

    int jm = j > 0 ? j - 1 : 0;
    int jp = j < SI - 1 ? j + 1 : SI - 1;

    const float* r0 = gp + iy0 * SI;
    const float* r1 = gp + iy1 * SI;
    float a0 = r0[jm], a1 = r0[j], a2 = r0[jp];
    float b0 = r1[jm], b1 = r1[j], b2 = r1[jp];

    // even pixel (x=2j): v00 = col jm, v01 = col j, fx = 0.75
    float topE = a0 + 0.75f * (a1 - a0);
    float botE = b0 + 0.75f * (b1 - b0);
    // odd pixel (x=2j+1): v00 = col j, v01 = col jp, fx = 0.25
    float topO = a1 + 0.25f * (a2 - a1);
    float botO = b1 + 0.25f * (b2 - b1);

    float2 res;
    res.x = topE + fy * (botE - topE);
    res.y = topO + fy * (botO - topO);

    long o = (((long)(b * C + c) * S + y) * S) + 2 * j;
    *reinterpret_cast<float2*>(out + o) = res;
}

// ---------------------------------------------------------------------------
// kernel_launch
// ---------------------------------------------------------------------------
extern "C" void kernel_launch(void* const* d_in, const int* in_sizes, int n_in,
                              void* d_out, int out_size)
{
    (void)in_sizes; (void)n_in; (void)out_size;

    const float* f1      = (const float*)d_in[0];
    const float* f2      = (const float*)d_in[1];
    const float* f3      = (const float*)d_in[2];
    const float* f4      = (const float*)d_in[3];
    const float* x_final = (const float*)d_in[4];
    const float* cw1     = (const float*)d_in[5];
    const float* cb1     = (const float*)d_in[6];
    const float* cw2     = (const float*)d_in[7];
    const float* cb2     = (const float*)d_in[8];
    const float* cw3     = (const float*)d_in[9];
    const float* cb3     = (const float*)d_in[10];
    const float* cw4     = (const float*)d_in[11];
    const float* cb4     = (const float*)d_in[12];
    const float* w1      = (const float*)d_in[13];
    const float* w2      = (const float*)d_in[14];
    const float* w3      = (const float*)d_in[15];
    const float* w4      = (const float*)d_in[16];
    const int*   perms   = (const int*)  d_in[17];

    float* out = (float*)d_out;

    float *g1, *g2, *g3;
    cudaGetSymbolAddress((void**)&g1, g1_scratch);
    cudaGetSymbolAddress((void**)&g2, g2_scratch);
    cudaGetSymbolAddress((void**)&g3, g3_scratch);

    // Output offsets (floats)
    constexpr long OFF_XF   = 0;
    constexpr long OFF_AUX1 = 32768;
    constexpr long OFF_AUX2 = 12877824;
    constexpr long OFF_AUX3 = 19300352;
    constexpr long OFF_AUX4 = 22511616;
    constexpr long OFF_W1   = 24117248;
    constexpr long OFF_W2   = 24317952;
    constexpr long OFF_W3   = 24418304;
    constexpr long OFF_W4   = 24468480;

    // Passthrough copies
    cudaMemcpyAsync(out + OFF_XF, x_final, 32768 * sizeof(float),
                    cudaMemcpyDeviceToDevice, 0);
    cudaMemcpyAsync(out + OFF_W1, w1, 200704 * sizeof(float),
                    cudaMemcpyDeviceToDevice, 0);
    cudaMemcpyAsync(out + OFF_W2, w2, 100352 * sizeof(float),
                    cudaMemcpyDeviceToDevice, 0);
    cudaMemcpyAsync(out + OFF_W3, w3, 50176 * sizeof(float),
                    cudaMemcpyDeviceToDevice, 0);
    cudaMemcpyAsync(out + OFF_W4, w4, 25088 * sizeof(float),
                    cudaMemcpyDeviceToDevice, 0);

    // Convs at source resolution. Flat N = 64*P, 64x64 tiles (R1 geometry).
    conv1x1_kernel<64, 64, 784><<<dim3(784, 1), 256>>>(f1, cw1, cb1, g1);
    conv1x1_kernel<128, 128, 196><<<dim3(196, 2), 256>>>(f2, cw2, cb2, g2);
    conv1x1_kernel<256, 128, 49><<<dim3(49, 4), 256>>>(f3, cw3, cb3, g3);
    // aux4: no upsample (7 -> 7), write output region directly.
    conv1x1_kernel<512, 512, 49><<<dim3(49, 8), 256>>>(f4, cw4, cb4,
                                                       out + OFF_AUX4);

    // Upsamples (pair-per-thread; aux1 fused with channel shuffle).
    upsample2x_kernel<64, 28, true><<<25088, 256>>>(g1, out + OFF_AUX1, perms);
    upsample2x_kernel<128, 14, false><<<12544, 256>>>(g2, out + OFF_AUX2, nullptr);
    upsample2x_kernel<256, 7, false><<<6272, 256>>>(g3, out + OFF_AUX3, nullptr);
}

// round 15
// speedup vs baseline: 1.5878x; 1.0675x over previous
#include <cuda_runtime.h>
#include <cstdint>

// ---------------------------------------------------------------------------
// ClientBackbone: 4x (conv1x1 [+ bilinear 2x upsample] [+ block shuffle])
// plus passthrough copies.
//
// Conv and bilinear-upsample commute (both linear), so convs run at source
// resolution (4x fewer FLOPs for layers 1-3) and the upsample runs after.
//
// R13-R15: conv GEMMs on tensor cores via mma.sync m16n8k8 TF32 with the
// 3xTF32 decomposition (hi*hi + hi*lo + lo*hi) for fp32-level accuracy.
// Evidence: fma-pipe cycles conserved at ~22.6us for L4 across R1/R8/R11/R12
// while tensor=0% — the FFMA path is at its floor; the tensor pipe is idle.
// R12's double-buffered loader and tiling retained; smem rows padded to 72
// floats for conflict-free fragment LDS. Upsample: pixel-pair per thread
// (validated R8/R12).
// ---------------------------------------------------------------------------

static constexpr int BATCH = 64;

// Scratch for conv outputs at source resolution (allocation-free rule).
__device__ float g1_scratch[BATCH * 64 * 28 * 28];    // 3,211,264
__device__ float g2_scratch[BATCH * 128 * 14 * 14];   // 1,605,632
__device__ float g3_scratch[BATCH * 256 * 7 * 7];     //   802,816

// Split fp32 into tf32-hi and tf32(residual).
__device__ __forceinline__ void cvt_split(float v, uint32_t& hi, uint32_t& lo)
{
    uint32_t h;
    asm("cvt.rna.tf32.f32 %0, %1;" : "=r"(h) : "f"(v));
    float r = v - __uint_as_float(h);
    uint32_t l;
    asm("cvt.rna.tf32.f32 %0, %1;" : "=r"(l) : "f"(r));
    hi = h; lo = l;
}

__device__ __forceinline__ void mma_tf32(float* c, const uint32_t* a,
                                         const uint32_t* b)
{
    asm volatile(
        "mma.sync.aligned.m16n8k8.row.col.f32.tf32.tf32.f32 "
        "{%0,%1,%2,%3}, {%4,%5,%6,%7}, {%8,%9}, {%0,%1,%2,%3};"
        : "+f"(c[0]), "+f"(c[1]), "+f"(c[2]), "+f"(c[3])
        : "r"(a[0]), "r"(a[1]), "r"(a[2]), "r"(a[3]),
          "r"(b[0]), "r"(b[1]));
}

// ---------------------------------------------------------------------------
// conv1x1: out[b, m, p] = sum_k w[m, k] * f[b, k, p] + bias[m]
// GEMM over flat n = b*P + p (N = 64*P, divisible by 64).
// 256 threads (8 warps = 2m x 4n), block tile 64M x 64N, K-tile 16.
// Warp tile 32m x 16n = 2x2 m16n8k8 mma tiles, 2 k-chunks per k-tile.
// Double-buffered smem, one barrier per k-tile (R12 structure).
// ---------------------------------------------------------------------------
template <int M, int K, int P>
__global__ __launch_bounds__(256) void conv1x1_kernel(
    const float* __restrict__ f, const float* __restrict__ w,
    const float* __restrict__ bias, float* __restrict__ out)
{
    __shared__ float ws[2][16][72];   // [buf][k][m], stride 72: conflict-free frags
    __shared__ float fs[2][16][72];   // [buf][k][n]
    __shared__ int   foff[64];        // per-n input base offset (b*K*P + p)
    __shared__ int   ooff[64];        // per-n output base offset (b*M*P + p)

    const int tid = threadIdx.x;
    const int n0 = blockIdx.x * 64;
    const int m0 = blockIdx.y * 64;

    if (tid < 64) {
        int nn = n0 + tid;
        int b = nn / P;
        int p = nn - b * P;
        foff[tid] = b * (K * P) + p;
        ooff[tid] = b * (M * P) + p;
    }
    __syncthreads();   // foff/ooff ready for prefetch below

    const int lane   = tid & 31;
    const int wid    = tid >> 5;
    const int warp_m = wid >> 2;   // 0..1  -> 32 m-rows each
    const int warp_n = wid & 3;    // 0..3  -> 16 n-cols each
    const int g  = lane >> 2;      // groupID (0..7)
    const int tg = lane & 3;       // thread-in-group (0..3)

    float acc[2][2][4];
#pragma unroll
    for (int i = 0; i < 2; i++)
#pragma unroll
        for (int j = 0; j < 2; j++)
#pragma unroll
            for (int r = 0; r < 4; r++) acc[i][j][r] = 0.0f;

    float wreg[4];
    float freg[4];

    // Prefetch tile 0 into registers
#pragma unroll
    for (int i = 0; i < 4; i++) {
        int e = tid + 256 * i;
        wreg[i] = w[(m0 + (e >> 4)) * K + (e & 15)];
        freg[i] = f[foff[e & 63] + (e >> 6) * P];
    }
#pragma unroll
    for (int i = 0; i < 4; i++) {
        int e = tid + 256 * i;
        ws[0][e & 15][e >> 4] = wreg[i];
        fs[0][e >> 6][e & 63] = freg[i];
    }
    __syncthreads();

    constexpr int NT = K / 16;
#pragma unroll 1
    for (int kt = 0; kt < NT; kt++) {
        const int cur = kt & 1;

        // Issue LDGs for tile kt+1 (latency overlapped with compute below)
        if (kt + 1 < NT) {
            const int k0 = (kt + 1) * 16;
#pragma unroll
            for (int i = 0; i < 4; i++) {
                int e = tid + 256 * i;
                wreg[i] = w[(m0 + (e >> 4)) * K + (k0 + (e & 15))];
                freg[i] = f[foff[e & 63] + (k0 + (e >> 6)) * P];
            }
        }

        // Compute: 2 k-chunks of 8
#pragma unroll
        for (int kc = 0; kc < 2; kc++) {
            uint32_t ahi[2][4], alo[2][4];
            uint32_t bhi[2][2], blo[2][2];

            // A fragments (row-major m16k8): rows m, cols k
#pragma unroll
            for (int mt = 0; mt < 2; mt++) {
                int r0 = warp_m * 32 + mt * 16 + g;
                int r1 = r0 + 8;
                int c0 = kc * 8 + tg;
                int c1 = c0 + 4;
                cvt_split(ws[cur][c0][r0], ahi[mt][0], alo[mt][0]);
                cvt_split(ws[cur][c0][r1], ahi[mt][1], alo[mt][1]);
                cvt_split(ws[cur][c1][r0], ahi[mt][2], alo[mt][2]);
                cvt_split(ws[cur][c1][r1], ahi[mt][3], alo[mt][3]);
            }
            // B fragments (col-major k8n8): rows k, cols n
#pragma unroll
            for (int nt = 0; nt < 2; nt++) {
                int nloc = warp_n * 16 + nt * 8 + g;
                int k0r = kc * 8 + tg;
                cvt_split(fs[cur][k0r][nloc],     bhi[nt][0], blo[nt][0]);
                cvt_split(fs[cur][k0r + 4][nloc], bhi[nt][1], blo[nt][1]);
            }

            // 3xTF32: hi*hi + hi*lo + lo*hi
#pragma unroll
            for (int mt = 0; mt < 2; mt++)
#pragma unroll
                for (int nt = 0; nt < 2; nt++) {
                    mma_tf32(acc[mt][nt], ahi[mt], blo[nt]);
                    mma_tf32(acc[mt][nt], alo[mt], bhi[nt]);
                    mma_tf32(acc[mt][nt], ahi[mt], bhi[nt]);
                }
        }

        // Store tile kt+1 into the other buffer; one barrier per k-tile.
        if (kt + 1 < NT) {
            const int nxt = 1 - cur;
#pragma unroll
            for (int i = 0; i < 4; i++) {
                int e = tid + 256 * i;
                ws[nxt][e & 15][e >> 4] = wreg[i];
                fs[nxt][e >> 6][e & 63] = freg[i];
            }
            __syncthreads();
        }
    }

    // Epilogue: C fragment rows g/g+8, cols 2*tg/2*tg+1 within each tile.
#pragma unroll
    for (int mt = 0; mt < 2; mt++) {
        int row0 = m0 + warp_m * 32 + mt * 16 + g;
        int row1 = row0 + 8;
        float bv0 = bias[row0];
        float bv1 = bias[row1];
#pragma unroll
        for (int nt = 0; nt < 2; nt++) {
            int cb = warp_n * 16 + nt * 8 + 2 * tg;
            out[ooff[cb]     + row0 * P] = acc[mt][nt][0] + bv0;
            out[ooff[cb + 1] + row0 * P] = acc[mt][nt][1] + bv0;
            out[ooff[cb]     + row1 * P] = acc[mt][nt][2] + bv1;
            out[ooff[cb + 1] + row1 * P] = acc[mt][nt][3] + bv1;
        }
    }
}

// ---------------------------------------------------------------------------
// Bilinear 2x upsample, half-pixel (align_corners=False), clamped edges.
// One thread per even/odd x-pair; shared source columns, one float2 store.
// For SHUF (aux1): both pixels of a pair share the shuffle block.
// ---------------------------------------------------------------------------
template <int C, int SI, bool SHUF>
__global__ __launch_bounds__(256) void upsample2x_kernel(
    const float* __restrict__ g, float* __restrict__ out,
    const int* __restrict__ perms)
{
    constexpr int S = SI * 2;
    constexpr int TOTAL = BATCH * C * S * SI;   // pairs
    int t = blockIdx.x * 256 + threadIdx.x;
    if (t >= TOTAL) return;

    int j = t % SI;
    int y = (t / SI) % S;
    int c = (t / (SI * S)) % C;
    int b = t / (SI * S * C);

    int cs = c;
    if (SHUF) {
        int blk = ((y >= 28) ? 2 : 0) + ((j >= 14) ? 1 : 0);
        cs = perms[blk * 64 + c];
    }
    const float* gp = g + (b * C + cs) * (SI * SI);

    int iy = (y - 1) >> 1;
    int iy0 = iy < 0 ? 0 : iy;
    int iy1 = (iy + 1 > SI - 1) ? SI - 1 : iy + 1;
    float fy = (y & 1) ? 0.25f : 0.75f;

    int jm = j > 0 ? j - 1 : 0;
    int jp = j < SI - 1 ? j + 1 : SI - 1;

    const float* r0 = gp + iy0 * SI;
    const float* r1 = gp + iy1 * SI;
    float a0 = r0[jm], a1 = r0[j], a2 = r0[jp];
    float b0 = r1[jm], b1 = r1[j], b2 = r1[jp];

    float topE = a0 + 0.75f * (a1 - a0);
    float botE = b0 + 0.75f * (b1 - b0);
    float topO = a1 + 0.25f * (a2 - a1);
    float botO = b1 + 0.25f * (b2 - b1);

    float2 res;
    res.x = topE + fy * (botE - topE);
    res.y = topO + fy * (botO - topO);

    long o = (((long)(b * C + c) * S + y) * S) + 2 * j;
    *reinterpret_cast<float2*>(out + o) = res;
}

// ---------------------------------------------------------------------------
// kernel_launch
// ---------------------------------------------------------------------------
extern "C" void kernel_launch(void* const* d_in, const int* in_sizes, int n_in,
                              void* d_out, int out_size)
{
    (void)in_sizes; (void)n_in; (void)out_size;

    const float* f1      = (const float*)d_in[0];
    const float* f2      = (const float*)d_in[1];
    const float* f3      = (const float*)d_in[2];
    const float* f4      = (const float*)d_in[3];
    const float* x_final = (const float*)d_in[4];
    const float* cw1     = (const float*)d_in[5];
    const float* cb1     = (const float*)d_in[6];
    const float* cw2     = (const float*)d_in[7];
    const float* cb2     = (const float*)d_in[8];
    const float* cw3     = (const float*)d_in[9];
    const float* cb3     = (const float*)d_in[10];
    const float* cw4     = (const float*)d_in[11];
    const float* cb4     = (const float*)d_in[12];
    const float* w1      = (const float*)d_in[13];
    const float* w2      = (const float*)d_in[14];
    const float* w3      = (const float*)d_in[15];
    const float* w4      = (const float*)d_in[16];
    const int*   perms   = (const int*)  d_in[17];

    float* out = (float*)d_out;

    float *g1, *g2, *g3;
    cudaGetSymbolAddress((void**)&g1, g1_scratch);
    cudaGetSymbolAddress((void**)&g2, g2_scratch);
    cudaGetSymbolAddress((void**)&g3, g3_scratch);

    // Output offsets (floats)
    constexpr long OFF_XF   = 0;
    constexpr long OFF_AUX1 = 32768;
    constexpr long OFF_AUX2 = 12877824;
    constexpr long OFF_AUX3 = 19300352;
    constexpr long OFF_AUX4 = 22511616;
    constexpr long OFF_W1   = 24117248;
    constexpr long OFF_W2   = 24317952;
    constexpr long OFF_W3   = 24418304;
    constexpr long OFF_W4   = 24468480;

    // Passthrough copies
    cudaMemcpyAsync(out + OFF_XF, x_final, 32768 * sizeof(float),
                    cudaMemcpyDeviceToDevice, 0);
    cudaMemcpyAsync(out + OFF_W1, w1, 200704 * sizeof(float),
                    cudaMemcpyDeviceToDevice, 0);
    cudaMemcpyAsync(out + OFF_W2, w2, 100352 * sizeof(float),
                    cudaMemcpyDeviceToDevice, 0);
    cudaMemcpyAsync(out + OFF_W3, w3, 50176 * sizeof(float),
                    cudaMemcpyDeviceToDevice, 0);
    cudaMemcpyAsync(out + OFF_W4, w4, 25088 * sizeof(float),
                    cudaMemcpyDeviceToDevice, 0);

    // Convs at source resolution. Flat N = 64*P, 64x64 tiles.
    conv1x1_kernel<64, 64, 784><<<dim3(784, 1), 256>>>(f1, cw1, cb1, g1);
    conv1x1_kernel<128, 128, 196><<<dim3(196, 2), 256>>>(f2, cw2, cb2, g2);
    conv1x1_kernel<256, 128, 49><<<dim3(49, 4), 256>>>(f3, cw3, cb3, g3);
    // aux4: no upsample (7 -> 7), write output region directly.
    conv1x1_kernel<512, 512, 49><<<dim3(49, 8), 256>>>(f4, cw4, cb4,
                                                       out + OFF_AUX4);

    // Upsamples (pair-per-thread; aux1 fused with channel shuffle).
    upsample2x_kernel<64, 28, true><<<25088, 256>>>(g1, out + OFF_AUX1, perms);
    upsample2x_kernel<128, 14, false><<<12544, 256>>>(g2, out + OFF_AUX2, nullptr);
    upsample2x_kernel<256, 7, false><<<6272, 256>>>(g3, out + OFF_AUX3, nullptr);
}